// round 8
// baseline (speedup 1.0000x reference)
#include <cuda_runtime.h>
#include <cuda_bf16.h>
#include <cuda_fp16.h>
#include <math.h>
#include <stdint.h>

#define NN 50000
#define EE 1600000
#define ET (EE + NN)
#define HID 128
#define FIN 39

#define SCAN_B 64
#define SCAN_CH ((NN + SCAN_B - 1) / SCAN_B)  // 782 nodes per scan block

// ---------------- scratch (device globals; no allocation allowed) ----------------
__device__ float g_h[NN * HID];
__device__ float g_tmp[NN * HID];
__device__ __half g_xph[NN * HID];  // fp16 xp (gather is the only consumer)
__device__ float g_es[NN * 4];
__device__ float g_ed[NN * 4];
__device__ float g_hidA[NN * 64];
__device__ float g_hidB[NN * 64];
__device__ int g_deg[NN];
__device__ int g_rowstart[NN + 1];
__device__ int g_cursor[NN];
__device__ int g_csrc[ET];
__device__ int g_bsum[SCAN_B];
__device__ int g_bbase[SCAN_B];
__device__ int g_esmaxI[12];  // per-layer (3) x per-head (4) order-encoded float max
// pre-split weight images, linear [N][K] bf16
__device__ __nv_bfloat16 g_wHi[6 * 128 * 128];
__device__ __nv_bfloat16 g_wLo[6 * 128 * 128];

__device__ __forceinline__ int f2o(float f) {
    int i = __float_as_int(f);
    return i >= 0 ? i : (i ^ 0x7fffffff);
}
__device__ __forceinline__ float o2f(int i) {
    return __int_as_float(i >= 0 ? i : (i ^ 0x7fffffff));
}

// ---------------- CSR build ----------------
__global__ void init_deg_k() {
    int i = blockIdx.x * blockDim.x + threadIdx.x;
    if (i < NN) g_deg[i] = 1;  // self-loop pre-counted
    if (i < 12) g_esmaxI[i] = 0x80000000;  // order-encoded -inf
}

__global__ void count_k(const int* __restrict__ ei) {
    int idx = blockIdx.x * blockDim.x + threadIdx.x;
    if (idx >= EE) return;
    atomicAdd(&g_deg[ei[EE + idx]], 1);
}

// phase 1: per-block chunk sums of deg
__global__ void __launch_bounds__(256) partial_k() {
    __shared__ int ws[8];
    int b = blockIdx.x, t = threadIdx.x;
    int lo = b * SCAN_CH, hi = min(lo + SCAN_CH, NN);
    int s = 0;
    for (int i = lo + t; i < hi; i += 256) s += g_deg[i];
#pragma unroll
    for (int off = 16; off >= 1; off >>= 1) s += __shfl_xor_sync(0xffffffffu, s, off);
    if ((t & 31) == 0) ws[t >> 5] = s;
    __syncthreads();
    if (t < 8) {
        int v = ws[t];
#pragma unroll
        for (int off = 4; off >= 1; off >>= 1) v += __shfl_xor_sync(0xffu, v, off);
        if (t == 0) g_bsum[b] = v;
    }
}

// phase 2: exclusive scan of the 64 block sums
__global__ void __launch_bounds__(64) scanb_k() {
    __shared__ int sh[SCAN_B];
    int t = threadIdx.x;
    int v = g_bsum[t];
    sh[t] = v;
    __syncthreads();
    for (int off = 1; off < SCAN_B; off <<= 1) {
        int u = (t >= off) ? sh[t - off] : 0;
        __syncthreads();
        sh[t] += u;
        __syncthreads();
    }
    g_bbase[t] = (t == 0) ? 0 : sh[t - 1];
    if (t == 0) g_rowstart[NN] = ET;
}

// phase 3: local re-scan + write rowstart/cursor/self-loop csrc
__global__ void __launch_bounds__(256) fill_k() {
    __shared__ int sh[256];
    int b = blockIdx.x, t = threadIdx.x;
    int lo = b * SCAN_CH, hi = min(lo + SCAN_CH, NN);
    const int CH2 = (SCAN_CH + 255) / 256;  // 4
    int mylo = lo + t * CH2;
    int myhi = min(mylo + CH2, hi);
    int s = 0;
    for (int i = mylo; i < myhi; i++) s += g_deg[i];
    sh[t] = s;
    __syncthreads();
    for (int off = 1; off < 256; off <<= 1) {
        int u = (t >= off) ? sh[t - off] : 0;
        __syncthreads();
        sh[t] += u;
        __syncthreads();
    }
    int base = g_bbase[b] + ((t == 0) ? 0 : sh[t - 1]);
    for (int i = mylo; i < myhi; i++) {
        g_rowstart[i] = base;
        g_csrc[base] = i;       // self-loop pre-placed
        g_cursor[i] = base + 1;
        base += g_deg[i];
    }
}

__global__ void scatter_k(const int* __restrict__ ei) {
    int idx = blockIdx.x * blockDim.x + threadIdx.x;
    if (idx >= EE) return;
    int s = ei[idx], d = ei[EE + idx];
    int p = atomicAdd(&g_cursor[d], 1);
    g_csrc[p] = s;
}

// ---------------- weight prep: transpose + bf16 hi/lo split, linear [N][K] ----------------
__global__ void __launch_bounds__(256) prep_w_k(const float* __restrict__ w0,
                                                const float* __restrict__ w1,
                                                const float* __restrict__ w2,
                                                const float* __restrict__ w3,
                                                const float* __restrict__ w4,
                                                const float* __restrict__ w5) {
    const float* Wm[6] = {w0, w1, w2, w3, w4, w5};
    const int ncs[6] = {128, 128, 128, 128, 64, 64};
    const int bases[6] = {0, 16384, 32768, 49152, 65536, 65536 + 8192};  // imp+tim packed
    int m = blockIdx.x;
    const float* B = Wm[m];
    int NC = ncs[m];
    __nv_bfloat16* hi = g_wHi + bases[m];
    __nv_bfloat16* lo = g_wLo + bases[m];
    int total = NC * 128;
    for (int i = threadIdx.x; i < total; i += 256) {
        int n = i >> 7, k = i & 127;
        float b = B[k * NC + n];
        __nv_bfloat16 h = __float2bfloat16(b);
        hi[i] = h;
        lo[i] = __float2bfloat16(b - __bfloat162float(h));
    }
}

// ---------------- encoder layer 1 (K=39, FFMA) ----------------
__global__ void __launch_bounds__(128) enc1_k(const float* __restrict__ x,
                                              const float* __restrict__ W,
                                              const float* __restrict__ b,
                                              float* __restrict__ out) {
    __shared__ float Ws[FIN * 128];
    __shared__ float xs[4 * FIN];
    int t = threadIdx.x;
    for (int i = t; i < FIN * 128; i += 128) Ws[i] = W[i];
    float bb = b[t];
    for (int r0 = blockIdx.x * 4; r0 < NN; r0 += gridDim.x * 4) {
        __syncthreads();
        for (int i = t; i < 4 * FIN; i += 128) {
            int rr = i / FIN, k = i % FIN;
            int row = r0 + rr;
            xs[i] = (row < NN) ? x[row * FIN + k] : 0.f;
        }
        __syncthreads();
        float a0 = 0.f, a1 = 0.f, a2 = 0.f, a3 = 0.f;
#pragma unroll
        for (int k = 0; k < FIN; k++) {
            float w = Ws[k * 128 + t];
            a0 = fmaf(xs[k], w, a0);
            a1 = fmaf(xs[FIN + k], w, a1);
            a2 = fmaf(xs[2 * FIN + k], w, a2);
            a3 = fmaf(xs[3 * FIN + k], w, a3);
        }
        float acc[4] = {a0, a1, a2, a3};
#pragma unroll
        for (int rr = 0; rr < 4; rr++) {
            int row = r0 + rr;
            if (row < NN) out[row * 128 + t] = fmaxf(acc[rr] + bb, 0.f);
        }
    }
}

// ---------------- HMMA GEMM core pieces ----------------
#define LDB 272  // padded smem row stride in bytes (136 bf16)

#define MMA16816(d, A0, A1, A2, A3, B0, B1)                                     \
    asm volatile(                                                               \
        "mma.sync.aligned.m16n8k16.row.col.f32.bf16.bf16.f32 "                  \
        "{%0,%1,%2,%3}, {%4,%5,%6,%7}, {%8,%9}, {%0,%1,%2,%3};"                 \
        : "+f"((d)[0]), "+f"((d)[1]), "+f"((d)[2]), "+f"((d)[3])                \
        : "r"(A0), "r"(A1), "r"(A2), "r"(A3), "r"(B0), "r"(B1))

// fill A (fp32 -> bf16 hi/lo split) + B (pre-split) into padded smem
template <int NC>
__device__ __forceinline__ void gemm_fill(const float* A, const __nv_bfloat16* Bhi,
                                          const __nv_bfloat16* Blo, char* sAhi,
                                          char* sAlo, char* sBhi, char* sBlo,
                                          int rb, int nrows, int tid) {
    for (int i = tid; i < 128 * 32; i += 256) {
        int r = i >> 5, c4 = (i & 31) * 4;
        float4 v = make_float4(0.f, 0.f, 0.f, 0.f);
        if (rb + r < nrows) v = *(const float4*)(A + (rb + r) * 128 + c4);
        __nv_bfloat16 h0 = __float2bfloat16(v.x), h1 = __float2bfloat16(v.y);
        __nv_bfloat16 h2 = __float2bfloat16(v.z), h3 = __float2bfloat16(v.w);
        __nv_bfloat16 l0 = __float2bfloat16(v.x - __bfloat162float(h0));
        __nv_bfloat16 l1 = __float2bfloat16(v.y - __bfloat162float(h1));
        __nv_bfloat16 l2 = __float2bfloat16(v.z - __bfloat162float(h2));
        __nv_bfloat16 l3 = __float2bfloat16(v.w - __bfloat162float(h3));
        __nv_bfloat162 ph0 = __halves2bfloat162(h0, h1), ph1 = __halves2bfloat162(h2, h3);
        __nv_bfloat162 pl0 = __halves2bfloat162(l0, l1), pl1 = __halves2bfloat162(l2, l3);
        int off = r * LDB + c4 * 2;
        *(uint2*)(sAhi + off) = make_uint2(*(uint32_t*)&ph0, *(uint32_t*)&ph1);
        *(uint2*)(sAlo + off) = make_uint2(*(uint32_t*)&pl0, *(uint32_t*)&pl1);
    }
    for (int i = tid; i < NC * 16; i += 256) {
        int n = i >> 4, k8 = (i & 15) * 8;
        int off = n * LDB + k8 * 2;
        *(uint4*)(sBhi + off) = ((const uint4*)Bhi)[i];
        *(uint4*)(sBlo + off) = ((const uint4*)Blo)[i];
    }
}

template <int NCH>
__device__ __forceinline__ void gemm_main(const char* sAhi, const char* sAlo,
                                          const char* sBhi, const char* sBlo,
                                          int lrow0, int g, int t, float acc[][4]) {
#pragma unroll
    for (int n = 0; n < NCH; n++)
#pragma unroll
        for (int j = 0; j < 4; j++) acc[n][j] = 0.f;
#pragma unroll
    for (int ks = 0; ks < 8; ks++) {
        int kb = ks * 32 + t * 4;
        const char* pa = sAhi + lrow0 * LDB + kb;
        uint32_t ah0 = *(const uint32_t*)(pa);
        uint32_t ah1 = *(const uint32_t*)(pa + 8 * LDB);
        uint32_t ah2 = *(const uint32_t*)(pa + 16);
        uint32_t ah3 = *(const uint32_t*)(pa + 8 * LDB + 16);
        const char* pl = sAlo + lrow0 * LDB + kb;
        uint32_t al0 = *(const uint32_t*)(pl);
        uint32_t al1 = *(const uint32_t*)(pl + 8 * LDB);
        uint32_t al2 = *(const uint32_t*)(pl + 16);
        uint32_t al3 = *(const uint32_t*)(pl + 8 * LDB + 16);
#pragma unroll
        for (int n = 0; n < NCH; n++) {
            int col = n * 8 + g;
            const char* pb = sBhi + col * LDB + kb;
            uint32_t bh0 = *(const uint32_t*)(pb);
            uint32_t bh1 = *(const uint32_t*)(pb + 16);
            const char* pbl = sBlo + col * LDB + kb;
            uint32_t bl0 = *(const uint32_t*)(pbl);
            uint32_t bl1 = *(const uint32_t*)(pbl + 16);
            MMA16816(acc[n], ah0, ah1, ah2, ah3, bh0, bh1);
            MMA16816(acc[n], ah0, ah1, ah2, ah3, bl0, bl1);
            MMA16816(acc[n], al0, al1, al2, al3, bh0, bh1);
        }
    }
}

// main GEMM: ATTN -> write fp16 xp + es/ed + global es max (no fp32 C); else fp32 C (+bias)(+relu)
template <int NC, bool HAS_BIAS, bool RELU, bool ATTN>
__global__ void __launch_bounds__(256) mma_gemm_k(const float* __restrict__ A,
                                                  const __nv_bfloat16* __restrict__ Bhi,
                                                  const __nv_bfloat16* __restrict__ Blo,
                                                  const float* __restrict__ bias,
                                                  const float* __restrict__ a_s,
                                                  const float* __restrict__ a_d,
                                                  int* __restrict__ esmaxI,
                                                  float* __restrict__ C, int nrows) {
    extern __shared__ char smem[];
    char* sAhi = smem;
    char* sAlo = smem + 34816;
    char* sBhi = smem + 69632;
    char* sBlo = sBhi + NC * LDB;
    __shared__ float s_max[8][4];

    int tid = threadIdx.x;
    int rb = blockIdx.x * 128;
    gemm_fill<NC>(A, Bhi, Blo, sAhi, sAlo, sBhi, sBlo, rb, nrows, tid);
    __syncthreads();

    int wid = tid >> 5, lane = tid & 31;
    int g = lane >> 2, t = lane & 3;
    int lrow0 = wid * 16 + g;
    constexpr int NCH = NC / 8;
    float acc[NCH][4];
    gemm_main<NCH>(sAhi, sAlo, sBhi, sBlo, lrow0, g, t, acc);

    int grow0 = rb + lrow0, grow1 = grow0 + 8;

    if (ATTN) {
        float es0[4], ed0[4], es1[4], ed1[4];
#pragma unroll
        for (int h = 0; h < 4; h++) { es0[h] = 0.f; ed0[h] = 0.f; es1[h] = 0.f; ed1[h] = 0.f; }
#pragma unroll
        for (int n = 0; n < NCH; n++) {
            int col = n * 8 + t * 2;
            int h = n >> 2;
            float as0 = __ldg(a_s + col), as1 = __ldg(a_s + col + 1);
            float ad0 = __ldg(a_d + col), ad1 = __ldg(a_d + col + 1);
            es0[h] += acc[n][0] * as0 + acc[n][1] * as1;
            ed0[h] += acc[n][0] * ad0 + acc[n][1] * ad1;
            es1[h] += acc[n][2] * as0 + acc[n][3] * as1;
            ed1[h] += acc[n][2] * ad0 + acc[n][3] * ad1;
        }
#pragma unroll
        for (int h = 0; h < 4; h++) {
            es0[h] += __shfl_xor_sync(0xffffffffu, es0[h], 1);
            es0[h] += __shfl_xor_sync(0xffffffffu, es0[h], 2);
            ed0[h] += __shfl_xor_sync(0xffffffffu, ed0[h], 1);
            ed0[h] += __shfl_xor_sync(0xffffffffu, ed0[h], 2);
            es1[h] += __shfl_xor_sync(0xffffffffu, es1[h], 1);
            es1[h] += __shfl_xor_sync(0xffffffffu, es1[h], 2);
            ed1[h] += __shfl_xor_sync(0xffffffffu, ed1[h], 1);
            ed1[h] += __shfl_xor_sync(0xffffffffu, ed1[h], 2);
        }
        if (t == 0) {
            if (grow0 < nrows) {
#pragma unroll
                for (int h = 0; h < 4; h++) {
                    g_es[grow0 * 4 + h] = es0[h];
                    g_ed[grow0 * 4 + h] = ed0[h];
                }
            }
            if (grow1 < nrows) {
#pragma unroll
                for (int h = 0; h < 4; h++) {
                    g_es[grow1 * 4 + h] = es1[h];
                    g_ed[grow1 * 4 + h] = ed1[h];
                }
            }
        }
        // block-level es max -> global atomicMax
        float wm[4];
#pragma unroll
        for (int h = 0; h < 4; h++) {
            wm[h] = fmaxf(es0[h], es1[h]);
#pragma unroll
            for (int off = 16; off >= 1; off >>= 1)
                wm[h] = fmaxf(wm[h], __shfl_xor_sync(0xffffffffu, wm[h], off));
        }
        if (lane == 0) {
#pragma unroll
            for (int h = 0; h < 4; h++) s_max[wid][h] = wm[h];
        }
        __syncthreads();
        if (wid == 0 && lane < 4) {
            float m = s_max[0][lane];
#pragma unroll
            for (int j = 1; j < 8; j++) m = fmaxf(m, s_max[j][lane]);
            atomicMax(&esmaxI[lane], f2o(m));
        }
        // store xp as fp16 only (gather is the sole consumer)
#pragma unroll
        for (int n = 0; n < NCH; n++) {
            int col = n * 8 + t * 2;
            __half2 p0 = __floats2half2_rn(acc[n][0], acc[n][1]);
            __half2 p1 = __floats2half2_rn(acc[n][2], acc[n][3]);
            if (grow0 < nrows) *(__half2*)(g_xph + grow0 * NC + col) = p0;
            if (grow1 < nrows) *(__half2*)(g_xph + grow1 * NC + col) = p1;
        }
        return;
    }

#pragma unroll
    for (int n = 0; n < NCH; n++) {
        int col = n * 8 + t * 2;
        float b0 = 0.f, b1 = 0.f;
        if (HAS_BIAS) { b0 = __ldg(bias + col); b1 = __ldg(bias + col + 1); }
        float o0 = acc[n][0] + b0, o1 = acc[n][1] + b1;
        float o2 = acc[n][2] + b0, o3 = acc[n][3] + b1;
        if (RELU) {
            o0 = fmaxf(o0, 0.f); o1 = fmaxf(o1, 0.f);
            o2 = fmaxf(o2, 0.f); o3 = fmaxf(o3, 0.f);
        }
        if (grow0 < nrows) *(float2*)(C + grow0 * NC + col) = make_float2(o0, o1);
        if (grow1 < nrows) *(float2*)(C + grow1 * NC + col) = make_float2(o2, o3);
    }
}

// fused heads GEMM: [imp_w1 | tim_w1] as one 128x128 B, split-store + relu
__global__ void __launch_bounds__(256) mma_heads_k(const float* __restrict__ A,
                                                   const __nv_bfloat16* __restrict__ Bhi,
                                                   const __nv_bfloat16* __restrict__ Blo,
                                                   const float* __restrict__ biasA,
                                                   const float* __restrict__ biasB,
                                                   int nrows) {
    extern __shared__ char smem[];
    char* sAhi = smem;
    char* sAlo = smem + 34816;
    char* sBhi = smem + 69632;
    char* sBlo = sBhi + 128 * LDB;

    int tid = threadIdx.x;
    int rb = blockIdx.x * 128;
    gemm_fill<128>(A, Bhi, Blo, sAhi, sAlo, sBhi, sBlo, rb, nrows, tid);
    __syncthreads();

    int wid = tid >> 5, lane = tid & 31;
    int g = lane >> 2, t = lane & 3;
    int lrow0 = wid * 16 + g;
    float acc[16][4];
    gemm_main<16>(sAhi, sAlo, sBhi, sBlo, lrow0, g, t, acc);

    int grow0 = rb + lrow0, grow1 = grow0 + 8;
#pragma unroll
    for (int n = 0; n < 16; n++) {
        int col = n * 8 + t * 2;
        bool isA = col < 64;
        int c2 = isA ? col : col - 64;
        float* dst = isA ? g_hidA : g_hidB;
        const float* bp = isA ? biasA : biasB;
        float b0 = __ldg(bp + c2), b1 = __ldg(bp + c2 + 1);
        float o0 = fmaxf(acc[n][0] + b0, 0.f), o1 = fmaxf(acc[n][1] + b1, 0.f);
        float o2 = fmaxf(acc[n][2] + b0, 0.f), o3 = fmaxf(acc[n][3] + b1, 0.f);
        if (grow0 < nrows) *(float2*)(dst + grow0 * 64 + c2) = make_float2(o0, o1);
        if (grow1 < nrows) *(float2*)(dst + grow1 * 64 + c2) = make_float2(o2, o3);
    }
}

// ---------------- gather: single-pass softmax-aggregate + bias + residual + LN + relu ----------------
__global__ void __launch_bounds__(256) gather_k(float* __restrict__ h,
                                                const float* __restrict__ bc,
                                                const float* __restrict__ gam,
                                                const float* __restrict__ bet,
                                                const int* __restrict__ esmaxI) {
    int d = (blockIdx.x * 256 + threadIdx.x) >> 5;
    if (d >= NN) return;
    int lane = threadIdx.x & 31;
    int hh = lane >> 3;
    float edc = g_ed[d * 4 + hh];
    // per-node upper bound on e = leaky(es + ed): c = leaky(esmax_h + ed) >= e (monotone)
    float c = o2f(esmaxI[hh]) + edc;
    c = (c > 0.f) ? c : 0.2f * c;
    int beg = g_rowstart[d], end = g_rowstart[d + 1];

    float ssum = 0.f;
    float4 acc = make_float4(0.f, 0.f, 0.f, 0.f);
    int i = beg;
    for (; i + 2 <= end; i += 2) {
        int s0 = __ldg(&g_csrc[i]);
        int s1 = __ldg(&g_csrc[i + 1]);
        float e0 = g_es[s0 * 4 + hh] + edc;
        float e1 = g_es[s1 * 4 + hh] + edc;
        e0 = (e0 > 0.f) ? e0 : 0.2f * e0;
        e1 = (e1 > 0.f) ? e1 : 0.2f * e1;
        float w0 = __expf(e0 - c);
        float w1 = __expf(e1 - c);
        uint2 r0 = *(const uint2*)(g_xph + s0 * 128 + lane * 4);
        uint2 r1 = *(const uint2*)(g_xph + s1 * 128 + lane * 4);
        float2 v0a = __half22float2(*(__half2*)&r0.x);
        float2 v0b = __half22float2(*(__half2*)&r0.y);
        float2 v1a = __half22float2(*(__half2*)&r1.x);
        float2 v1b = __half22float2(*(__half2*)&r1.y);
        ssum += w0 + w1;
        acc.x = fmaf(w0, v0a.x, fmaf(w1, v1a.x, acc.x));
        acc.y = fmaf(w0, v0a.y, fmaf(w1, v1a.y, acc.y));
        acc.z = fmaf(w0, v0b.x, fmaf(w1, v1b.x, acc.z));
        acc.w = fmaf(w0, v0b.y, fmaf(w1, v1b.y, acc.w));
    }
    if (i < end) {
        int s0 = __ldg(&g_csrc[i]);
        float e0 = g_es[s0 * 4 + hh] + edc;
        e0 = (e0 > 0.f) ? e0 : 0.2f * e0;
        float w0 = __expf(e0 - c);
        uint2 r0 = *(const uint2*)(g_xph + s0 * 128 + lane * 4);
        float2 v0a = __half22float2(*(__half2*)&r0.x);
        float2 v0b = __half22float2(*(__half2*)&r0.y);
        ssum += w0;
        acc.x = fmaf(w0, v0a.x, acc.x);
        acc.y = fmaf(w0, v0a.y, acc.y);
        acc.z = fmaf(w0, v0b.x, acc.z);
        acc.w = fmaf(w0, v0b.y, acc.w);
    }
    float inv = 1.f / ssum;

    float4 hv = *(const float4*)(h + d * 128 + lane * 4);
    float4 bcv = *(const float4*)(bc + lane * 4);
    float4 y;
    y.x = acc.x * inv + bcv.x + hv.x;
    y.y = acc.y * inv + bcv.y + hv.y;
    y.z = acc.z * inv + bcv.z + hv.z;
    y.w = acc.w * inv + bcv.w + hv.w;

    float s1v = y.x + y.y + y.z + y.w;
#pragma unroll
    for (int off = 16; off >= 1; off >>= 1) s1v += __shfl_xor_sync(0xffffffffu, s1v, off);
    float mean = s1v * (1.f / 128.f);
    float dx = y.x - mean, dy = y.y - mean, dz = y.z - mean, dw = y.w - mean;
    float sq = dx * dx + dy * dy + dz * dz + dw * dw;
#pragma unroll
    for (int off = 16; off >= 1; off >>= 1) sq += __shfl_xor_sync(0xffffffffu, sq, off);
    float rstd = rsqrtf(sq * (1.f / 128.f) + 1e-5f);

    float4 g4 = *(const float4*)(gam + lane * 4);
    float4 b4 = *(const float4*)(bet + lane * 4);
    float4 o;
    o.x = fmaxf(dx * rstd * g4.x + b4.x, 0.f);
    o.y = fmaxf(dy * rstd * g4.y + b4.y, 0.f);
    o.z = fmaxf(dz * rstd * g4.z + b4.z, 0.f);
    o.w = fmaxf(dw * rstd * g4.w + b4.w, 0.f);
    *(float4*)(h + d * 128 + lane * 4) = o;
}

// ---------------- output heads ----------------
__device__ __forceinline__ float softplusf(float x) {
    if (x > 20.f) return x;
    return log1pf(__expf(x));
}

__global__ void __launch_bounds__(256) heads_k(const float* __restrict__ w2i,
                                               const float* __restrict__ b2i,
                                               const float* __restrict__ w2t,
                                               const float* __restrict__ b2t,
                                               float* __restrict__ out) {
    __shared__ float wi[64 * 3];
    __shared__ float wt[64 * 2];
    int t = threadIdx.x;
    if (t < 192) wi[t] = w2i[t];
    if (t < 128) wt[t] = w2t[t];
    __syncthreads();
    int n = blockIdx.x * 256 + t;
    if (n >= NN) return;
    float a0 = 0.f, a1 = 0.f, a2 = 0.f;
#pragma unroll 8
    for (int k = 0; k < 64; k++) {
        float v = g_hidA[n * 64 + k];
        a0 = fmaf(v, wi[k * 3 + 0], a0);
        a1 = fmaf(v, wi[k * 3 + 1], a1);
        a2 = fmaf(v, wi[k * 3 + 2], a2);
    }
    out[n * 3 + 0] = a0 + b2i[0];
    out[n * 3 + 1] = a1 + b2i[1];
    out[n * 3 + 2] = a2 + b2i[2];
    float t0 = 0.f, t1 = 0.f;
#pragma unroll 8
    for (int k = 0; k < 64; k++) {
        float v = g_hidB[n * 64 + k];
        t0 = fmaf(v, wt[k * 2 + 0], t0);
        t1 = fmaf(v, wt[k * 2 + 1], t1);
    }
    out[3 * NN + n * 2 + 0] = softplusf(t0 + b2t[0]);
    out[3 * NN + n * 2 + 1] = softplusf(t1 + b2t[1]);
}

// ---------------- launch ----------------
extern "C" void kernel_launch(void* const* d_in, const int* in_sizes, int n_in,
                              void* d_out, int out_size) {
    const float* x      = (const float*)d_in[0];
    const int*   ei     = (const int*)d_in[1];
    const float* enc_w1 = (const float*)d_in[2];
    const float* enc_b1 = (const float*)d_in[3];
    const float* enc_w2 = (const float*)d_in[4];
    const float* enc_b2 = (const float*)d_in[5];
    const float* W[3]  = {(const float*)d_in[6],  (const float*)d_in[12], (const float*)d_in[18]};
    const float* As[3] = {(const float*)d_in[7],  (const float*)d_in[13], (const float*)d_in[19]};
    const float* Ad[3] = {(const float*)d_in[8],  (const float*)d_in[14], (const float*)d_in[20]};
    const float* Bc[3] = {(const float*)d_in[9],  (const float*)d_in[15], (const float*)d_in[21]};
    const float* Gm[3] = {(const float*)d_in[10], (const float*)d_in[16], (const float*)d_in[22]};
    const float* Be[3] = {(const float*)d_in[11], (const float*)d_in[17], (const float*)d_in[23]};
    const float* imp_w1 = (const float*)d_in[24];
    const float* imp_b1 = (const float*)d_in[25];
    const float* imp_w2 = (const float*)d_in[26];
    const float* imp_b2 = (const float*)d_in[27];
    const float* tim_w1 = (const float*)d_in[28];
    const float* tim_b1 = (const float*)d_in[29];
    const float* tim_w2 = (const float*)d_in[30];
    const float* tim_b2 = (const float*)d_in[31];
    float* out = (float*)d_out;

    float *p_h, *p_tmp;
    cudaGetSymbolAddress((void**)&p_h, g_h);
    cudaGetSymbolAddress((void**)&p_tmp, g_tmp);
    int* p_esmax;
    cudaGetSymbolAddress((void**)&p_esmax, g_esmaxI);
    __nv_bfloat16 *p_wHi, *p_wLo;
    cudaGetSymbolAddress((void**)&p_wHi, g_wHi);
    cudaGetSymbolAddress((void**)&p_wLo, g_wLo);

    const int SMEM_128 = 69632 + 2 * 128 * LDB;  // 139264
    cudaFuncSetAttribute((const void*)mma_gemm_k<128, true, false, false>,
                         cudaFuncAttributeMaxDynamicSharedMemorySize, SMEM_128);
    cudaFuncSetAttribute((const void*)mma_gemm_k<128, false, false, true>,
                         cudaFuncAttributeMaxDynamicSharedMemorySize, SMEM_128);
    cudaFuncSetAttribute((const void*)mma_heads_k,
                         cudaFuncAttributeMaxDynamicSharedMemorySize, SMEM_128);

    const int NB = (NN + 127) / 128;  // 391

    // weight prep + CSR build (parallel scan)
    prep_w_k<<<6, 256>>>(enc_w2, W[0], W[1], W[2], imp_w1, tim_w1);
    init_deg_k<<<(NN + 255) / 256, 256>>>();
    count_k<<<(EE + 255) / 256, 256>>>(ei);
    partial_k<<<SCAN_B, 256>>>();
    scanb_k<<<1, SCAN_B>>>();
    fill_k<<<SCAN_B, 256>>>();
    scatter_k<<<(EE + 255) / 256, 256>>>(ei);

    // encoder
    enc1_k<<<2048, 128>>>(x, enc_w1, enc_b1, p_tmp);
    mma_gemm_k<128, true, false, false><<<NB, 256, SMEM_128>>>(
        p_tmp, p_wHi, p_wLo, enc_b2, nullptr, nullptr, nullptr, p_h, NN);

    // 3 GAT layers (es/ed + es-max + fp16 xp in GEMM epilogue; single-pass gather)
    for (int l = 0; l < 3; l++) {
        mma_gemm_k<128, false, false, true><<<NB, 256, SMEM_128>>>(
            p_h, p_wHi + (1 + l) * 16384, p_wLo + (1 + l) * 16384, nullptr,
            As[l], Ad[l], p_esmax + l * 4, nullptr, NN);
        gather_k<<<(NN * 32 + 255) / 256, 256>>>(p_h, Bc[l], Gm[l], Be[l],
                                                 p_esmax + l * 4);
    }

    // fused heads
    mma_heads_k<<<NB, 256, SMEM_128>>>(p_h, p_wHi + 4 * 16384, p_wLo + 4 * 16384,
                                       imp_b1, tim_b1, NN);
    heads_k<<<(NN + 255) / 256, 256>>>(imp_w2, imp_b2, tim_w2, tim_b2, out);
}

// round 9
// speedup vs baseline: 1.0312x; 1.0312x over previous
#include <cuda_runtime.h>
#include <cuda_bf16.h>
#include <cuda_fp16.h>
#include <math.h>
#include <stdint.h>

#define NN 50000
#define EE 1600000
#define ET (EE + NN)
#define HID 128
#define FIN 39

#define SCAN_B 64
#define SCAN_CH ((NN + SCAN_B - 1) / SCAN_B)  // 782 nodes per scan block

// ---------------- scratch (device globals; no allocation allowed) ----------------
__device__ float g_h[NN * HID];
__device__ float g_tmp[NN * HID];
__device__ __half g_xph[NN * HID];  // fp16 xp (gather is the only consumer)
__device__ float g_es[NN * 4];
__device__ float g_ed[NN * 4];
__device__ float g_w[ET * 4];       // per-edge per-head softmax numerators
__device__ float g_hidA[NN * 64];
__device__ float g_hidB[NN * 64];
__device__ int g_deg[NN];
__device__ int g_rowstart[NN + 1];
__device__ int g_cursor[NN];
__device__ int g_csrc[ET];
__device__ int g_cdst[ET];
__device__ int g_bsum[SCAN_B];
__device__ int g_bbase[SCAN_B];
__device__ int g_esmaxI[12];  // per-layer (3) x per-head (4) order-encoded float max
// pre-split weight images, linear [N][K] bf16
__device__ __nv_bfloat16 g_wHi[6 * 128 * 128];
__device__ __nv_bfloat16 g_wLo[6 * 128 * 128];

__device__ __forceinline__ int f2o(float f) {
    int i = __float_as_int(f);
    return i >= 0 ? i : (i ^ 0x7fffffff);
}
__device__ __forceinline__ float o2f(int i) {
    return __int_as_float(i >= 0 ? i : (i ^ 0x7fffffff));
}

// ---------------- CSR build ----------------
__global__ void init_deg_k() {
    int i = blockIdx.x * blockDim.x + threadIdx.x;
    if (i < NN) g_deg[i] = 1;  // self-loop pre-counted
    if (i < 12) g_esmaxI[i] = 0x80000000;  // order-encoded -inf
}

__global__ void count_k(const int* __restrict__ ei) {
    int idx = blockIdx.x * blockDim.x + threadIdx.x;
    if (idx >= EE) return;
    atomicAdd(&g_deg[ei[EE + idx]], 1);
}

// phase 1: per-block chunk sums of deg
__global__ void __launch_bounds__(256) partial_k() {
    __shared__ int ws[8];
    int b = blockIdx.x, t = threadIdx.x;
    int lo = b * SCAN_CH, hi = min(lo + SCAN_CH, NN);
    int s = 0;
    for (int i = lo + t; i < hi; i += 256) s += g_deg[i];
#pragma unroll
    for (int off = 16; off >= 1; off >>= 1) s += __shfl_xor_sync(0xffffffffu, s, off);
    if ((t & 31) == 0) ws[t >> 5] = s;
    __syncthreads();
    if (t < 8) {
        int v = ws[t];
#pragma unroll
        for (int off = 4; off >= 1; off >>= 1) v += __shfl_xor_sync(0xffu, v, off);
        if (t == 0) g_bsum[b] = v;
    }
}

// phase 2: exclusive scan of the 64 block sums
__global__ void __launch_bounds__(64) scanb_k() {
    __shared__ int sh[SCAN_B];
    int t = threadIdx.x;
    int v = g_bsum[t];
    sh[t] = v;
    __syncthreads();
    for (int off = 1; off < SCAN_B; off <<= 1) {
        int u = (t >= off) ? sh[t - off] : 0;
        __syncthreads();
        sh[t] += u;
        __syncthreads();
    }
    g_bbase[t] = (t == 0) ? 0 : sh[t - 1];
    if (t == 0) g_rowstart[NN] = ET;
}

// phase 3: local re-scan + write rowstart/cursor/self-loop csrc+cdst
__global__ void __launch_bounds__(256) fill_k() {
    __shared__ int sh[256];
    int b = blockIdx.x, t = threadIdx.x;
    int lo = b * SCAN_CH, hi = min(lo + SCAN_CH, NN);
    const int CH2 = (SCAN_CH + 255) / 256;  // 4
    int mylo = lo + t * CH2;
    int myhi = min(mylo + CH2, hi);
    int s = 0;
    for (int i = mylo; i < myhi; i++) s += g_deg[i];
    sh[t] = s;
    __syncthreads();
    for (int off = 1; off < 256; off <<= 1) {
        int u = (t >= off) ? sh[t - off] : 0;
        __syncthreads();
        sh[t] += u;
        __syncthreads();
    }
    int base = g_bbase[b] + ((t == 0) ? 0 : sh[t - 1]);
    for (int i = mylo; i < myhi; i++) {
        g_rowstart[i] = base;
        g_csrc[base] = i;  // self-loop
        g_cdst[base] = i;
        g_cursor[i] = base + 1;
        base += g_deg[i];
    }
}

__global__ void scatter_k(const int* __restrict__ ei) {
    int idx = blockIdx.x * blockDim.x + threadIdx.x;
    if (idx >= EE) return;
    int s = ei[idx], d = ei[EE + idx];
    int p = atomicAdd(&g_cursor[d], 1);
    g_csrc[p] = s;
    g_cdst[p] = d;
}

// ---------------- weight prep: transpose + bf16 hi/lo split, linear [N][K] ----------------
__global__ void __launch_bounds__(256) prep_w_k(const float* __restrict__ w0,
                                                const float* __restrict__ w1,
                                                const float* __restrict__ w2,
                                                const float* __restrict__ w3,
                                                const float* __restrict__ w4,
                                                const float* __restrict__ w5) {
    const float* Wm[6] = {w0, w1, w2, w3, w4, w5};
    const int ncs[6] = {128, 128, 128, 128, 64, 64};
    const int bases[6] = {0, 16384, 32768, 49152, 65536, 65536 + 8192};  // imp+tim packed
    int m = blockIdx.x;
    const float* B = Wm[m];
    int NC = ncs[m];
    __nv_bfloat16* hi = g_wHi + bases[m];
    __nv_bfloat16* lo = g_wLo + bases[m];
    int total = NC * 128;
    for (int i = threadIdx.x; i < total; i += 256) {
        int n = i >> 7, k = i & 127;
        float b = B[k * NC + n];
        __nv_bfloat16 h = __float2bfloat16(b);
        hi[i] = h;
        lo[i] = __float2bfloat16(b - __bfloat162float(h));
    }
}

// ---------------- encoder layer 1 (K=39, FFMA) ----------------
__global__ void __launch_bounds__(128) enc1_k(const float* __restrict__ x,
                                              const float* __restrict__ W,
                                              const float* __restrict__ b,
                                              float* __restrict__ out) {
    __shared__ float Ws[FIN * 128];
    __shared__ float xs[4 * FIN];
    int t = threadIdx.x;
    for (int i = t; i < FIN * 128; i += 128) Ws[i] = W[i];
    float bb = b[t];
    for (int r0 = blockIdx.x * 4; r0 < NN; r0 += gridDim.x * 4) {
        __syncthreads();
        for (int i = t; i < 4 * FIN; i += 128) {
            int rr = i / FIN, k = i % FIN;
            int row = r0 + rr;
            xs[i] = (row < NN) ? x[row * FIN + k] : 0.f;
        }
        __syncthreads();
        float a0 = 0.f, a1 = 0.f, a2 = 0.f, a3 = 0.f;
#pragma unroll
        for (int k = 0; k < FIN; k++) {
            float w = Ws[k * 128 + t];
            a0 = fmaf(xs[k], w, a0);
            a1 = fmaf(xs[FIN + k], w, a1);
            a2 = fmaf(xs[2 * FIN + k], w, a2);
            a3 = fmaf(xs[3 * FIN + k], w, a3);
        }
        float acc[4] = {a0, a1, a2, a3};
#pragma unroll
        for (int rr = 0; rr < 4; rr++) {
            int row = r0 + rr;
            if (row < NN) out[row * 128 + t] = fmaxf(acc[rr] + bb, 0.f);
        }
    }
}

// ---------------- HMMA GEMM core pieces ----------------
#define LDB 272  // padded smem row stride in bytes (136 bf16)

#define MMA16816(d, A0, A1, A2, A3, B0, B1)                                     \
    asm volatile(                                                               \
        "mma.sync.aligned.m16n8k16.row.col.f32.bf16.bf16.f32 "                  \
        "{%0,%1,%2,%3}, {%4,%5,%6,%7}, {%8,%9}, {%0,%1,%2,%3};"                 \
        : "+f"((d)[0]), "+f"((d)[1]), "+f"((d)[2]), "+f"((d)[3])                \
        : "r"(A0), "r"(A1), "r"(A2), "r"(A3), "r"(B0), "r"(B1))

// fill A (fp32 -> bf16 hi/lo split) + B (pre-split) into padded smem
template <int NC>
__device__ __forceinline__ void gemm_fill(const float* A, const __nv_bfloat16* Bhi,
                                          const __nv_bfloat16* Blo, char* sAhi,
                                          char* sAlo, char* sBhi, char* sBlo,
                                          int rb, int nrows, int tid) {
    for (int i = tid; i < 128 * 32; i += 256) {
        int r = i >> 5, c4 = (i & 31) * 4;
        float4 v = make_float4(0.f, 0.f, 0.f, 0.f);
        if (rb + r < nrows) v = *(const float4*)(A + (rb + r) * 128 + c4);
        __nv_bfloat16 h0 = __float2bfloat16(v.x), h1 = __float2bfloat16(v.y);
        __nv_bfloat16 h2 = __float2bfloat16(v.z), h3 = __float2bfloat16(v.w);
        __nv_bfloat16 l0 = __float2bfloat16(v.x - __bfloat162float(h0));
        __nv_bfloat16 l1 = __float2bfloat16(v.y - __bfloat162float(h1));
        __nv_bfloat16 l2 = __float2bfloat16(v.z - __bfloat162float(h2));
        __nv_bfloat16 l3 = __float2bfloat16(v.w - __bfloat162float(h3));
        __nv_bfloat162 ph0 = __halves2bfloat162(h0, h1), ph1 = __halves2bfloat162(h2, h3);
        __nv_bfloat162 pl0 = __halves2bfloat162(l0, l1), pl1 = __halves2bfloat162(l2, l3);
        int off = r * LDB + c4 * 2;
        *(uint2*)(sAhi + off) = make_uint2(*(uint32_t*)&ph0, *(uint32_t*)&ph1);
        *(uint2*)(sAlo + off) = make_uint2(*(uint32_t*)&pl0, *(uint32_t*)&pl1);
    }
    for (int i = tid; i < NC * 16; i += 256) {
        int n = i >> 4, k8 = (i & 15) * 8;
        int off = n * LDB + k8 * 2;
        *(uint4*)(sBhi + off) = ((const uint4*)Bhi)[i];
        *(uint4*)(sBlo + off) = ((const uint4*)Blo)[i];
    }
}

template <int NCH>
__device__ __forceinline__ void gemm_main(const char* sAhi, const char* sAlo,
                                          const char* sBhi, const char* sBlo,
                                          int lrow0, int g, int t, float acc[][4]) {
#pragma unroll
    for (int n = 0; n < NCH; n++)
#pragma unroll
        for (int j = 0; j < 4; j++) acc[n][j] = 0.f;
#pragma unroll
    for (int ks = 0; ks < 8; ks++) {
        int kb = ks * 32 + t * 4;
        const char* pa = sAhi + lrow0 * LDB + kb;
        uint32_t ah0 = *(const uint32_t*)(pa);
        uint32_t ah1 = *(const uint32_t*)(pa + 8 * LDB);
        uint32_t ah2 = *(const uint32_t*)(pa + 16);
        uint32_t ah3 = *(const uint32_t*)(pa + 8 * LDB + 16);
        const char* pl = sAlo + lrow0 * LDB + kb;
        uint32_t al0 = *(const uint32_t*)(pl);
        uint32_t al1 = *(const uint32_t*)(pl + 8 * LDB);
        uint32_t al2 = *(const uint32_t*)(pl + 16);
        uint32_t al3 = *(const uint32_t*)(pl + 8 * LDB + 16);
#pragma unroll
        for (int n = 0; n < NCH; n++) {
            int col = n * 8 + g;
            const char* pb = sBhi + col * LDB + kb;
            uint32_t bh0 = *(const uint32_t*)(pb);
            uint32_t bh1 = *(const uint32_t*)(pb + 16);
            const char* pbl = sBlo + col * LDB + kb;
            uint32_t bl0 = *(const uint32_t*)(pbl);
            uint32_t bl1 = *(const uint32_t*)(pbl + 16);
            MMA16816(acc[n], ah0, ah1, ah2, ah3, bh0, bh1);
            MMA16816(acc[n], ah0, ah1, ah2, ah3, bl0, bl1);
            MMA16816(acc[n], al0, al1, al2, al3, bh0, bh1);
        }
    }
}

// main GEMM: ATTN -> write fp16 xp + es/ed + global es max (no fp32 C); else fp32 C (+bias)(+relu)
template <int NC, bool HAS_BIAS, bool RELU, bool ATTN>
__global__ void __launch_bounds__(256) mma_gemm_k(const float* __restrict__ A,
                                                  const __nv_bfloat16* __restrict__ Bhi,
                                                  const __nv_bfloat16* __restrict__ Blo,
                                                  const float* __restrict__ bias,
                                                  const float* __restrict__ a_s,
                                                  const float* __restrict__ a_d,
                                                  int* __restrict__ esmaxI,
                                                  float* __restrict__ C, int nrows) {
    extern __shared__ char smem[];
    char* sAhi = smem;
    char* sAlo = smem + 34816;
    char* sBhi = smem + 69632;
    char* sBlo = sBhi + NC * LDB;
    __shared__ float s_max[8][4];

    int tid = threadIdx.x;
    int rb = blockIdx.x * 128;
    gemm_fill<NC>(A, Bhi, Blo, sAhi, sAlo, sBhi, sBlo, rb, nrows, tid);
    __syncthreads();

    int wid = tid >> 5, lane = tid & 31;
    int g = lane >> 2, t = lane & 3;
    int lrow0 = wid * 16 + g;
    constexpr int NCH = NC / 8;
    float acc[NCH][4];
    gemm_main<NCH>(sAhi, sAlo, sBhi, sBlo, lrow0, g, t, acc);

    int grow0 = rb + lrow0, grow1 = grow0 + 8;

    if (ATTN) {
        float es0[4], ed0[4], es1[4], ed1[4];
#pragma unroll
        for (int h = 0; h < 4; h++) { es0[h] = 0.f; ed0[h] = 0.f; es1[h] = 0.f; ed1[h] = 0.f; }
#pragma unroll
        for (int n = 0; n < NCH; n++) {
            int col = n * 8 + t * 2;
            int h = n >> 2;
            float as0 = __ldg(a_s + col), as1 = __ldg(a_s + col + 1);
            float ad0 = __ldg(a_d + col), ad1 = __ldg(a_d + col + 1);
            es0[h] += acc[n][0] * as0 + acc[n][1] * as1;
            ed0[h] += acc[n][0] * ad0 + acc[n][1] * ad1;
            es1[h] += acc[n][2] * as0 + acc[n][3] * as1;
            ed1[h] += acc[n][2] * ad0 + acc[n][3] * ad1;
        }
#pragma unroll
        for (int h = 0; h < 4; h++) {
            es0[h] += __shfl_xor_sync(0xffffffffu, es0[h], 1);
            es0[h] += __shfl_xor_sync(0xffffffffu, es0[h], 2);
            ed0[h] += __shfl_xor_sync(0xffffffffu, ed0[h], 1);
            ed0[h] += __shfl_xor_sync(0xffffffffu, ed0[h], 2);
            es1[h] += __shfl_xor_sync(0xffffffffu, es1[h], 1);
            es1[h] += __shfl_xor_sync(0xffffffffu, es1[h], 2);
            ed1[h] += __shfl_xor_sync(0xffffffffu, ed1[h], 1);
            ed1[h] += __shfl_xor_sync(0xffffffffu, ed1[h], 2);
        }
        if (t == 0) {
            if (grow0 < nrows) {
#pragma unroll
                for (int h = 0; h < 4; h++) {
                    g_es[grow0 * 4 + h] = es0[h];
                    g_ed[grow0 * 4 + h] = ed0[h];
                }
            }
            if (grow1 < nrows) {
#pragma unroll
                for (int h = 0; h < 4; h++) {
                    g_es[grow1 * 4 + h] = es1[h];
                    g_ed[grow1 * 4 + h] = ed1[h];
                }
            }
        }
        // block-level es max -> global atomicMax
        float wm[4];
#pragma unroll
        for (int h = 0; h < 4; h++) {
            wm[h] = fmaxf(es0[h], es1[h]);
#pragma unroll
            for (int off = 16; off >= 1; off >>= 1)
                wm[h] = fmaxf(wm[h], __shfl_xor_sync(0xffffffffu, wm[h], off));
        }
        if (lane == 0) {
#pragma unroll
            for (int h = 0; h < 4; h++) s_max[wid][h] = wm[h];
        }
        __syncthreads();
        if (wid == 0 && lane < 4) {
            float m = s_max[0][lane];
#pragma unroll
            for (int j = 1; j < 8; j++) m = fmaxf(m, s_max[j][lane]);
            atomicMax(&esmaxI[lane], f2o(m));
        }
        // store xp as fp16 only (gather is the sole consumer)
#pragma unroll
        for (int n = 0; n < NCH; n++) {
            int col = n * 8 + t * 2;
            __half2 p0 = __floats2half2_rn(acc[n][0], acc[n][1]);
            __half2 p1 = __floats2half2_rn(acc[n][2], acc[n][3]);
            if (grow0 < nrows) *(__half2*)(g_xph + grow0 * NC + col) = p0;
            if (grow1 < nrows) *(__half2*)(g_xph + grow1 * NC + col) = p1;
        }
        return;
    }

#pragma unroll
    for (int n = 0; n < NCH; n++) {
        int col = n * 8 + t * 2;
        float b0 = 0.f, b1 = 0.f;
        if (HAS_BIAS) { b0 = __ldg(bias + col); b1 = __ldg(bias + col + 1); }
        float o0 = acc[n][0] + b0, o1 = acc[n][1] + b1;
        float o2 = acc[n][2] + b0, o3 = acc[n][3] + b1;
        if (RELU) {
            o0 = fmaxf(o0, 0.f); o1 = fmaxf(o1, 0.f);
            o2 = fmaxf(o2, 0.f); o3 = fmaxf(o3, 0.f);
        }
        if (grow0 < nrows) *(float2*)(C + grow0 * NC + col) = make_float2(o0, o1);
        if (grow1 < nrows) *(float2*)(C + grow1 * NC + col) = make_float2(o2, o3);
    }
}

// fused heads GEMM: [imp_w1 | tim_w1] as one 128x128 B, split-store + relu
__global__ void __launch_bounds__(256) mma_heads_k(const float* __restrict__ A,
                                                   const __nv_bfloat16* __restrict__ Bhi,
                                                   const __nv_bfloat16* __restrict__ Blo,
                                                   const float* __restrict__ biasA,
                                                   const float* __restrict__ biasB,
                                                   int nrows) {
    extern __shared__ char smem[];
    char* sAhi = smem;
    char* sAlo = smem + 34816;
    char* sBhi = smem + 69632;
    char* sBlo = sBhi + 128 * LDB;

    int tid = threadIdx.x;
    int rb = blockIdx.x * 128;
    gemm_fill<128>(A, Bhi, Blo, sAhi, sAlo, sBhi, sBlo, rb, nrows, tid);
    __syncthreads();

    int wid = tid >> 5, lane = tid & 31;
    int g = lane >> 2, t = lane & 3;
    int lrow0 = wid * 16 + g;
    float acc[16][4];
    gemm_main<16>(sAhi, sAlo, sBhi, sBlo, lrow0, g, t, acc);

    int grow0 = rb + lrow0, grow1 = grow0 + 8;
#pragma unroll
    for (int n = 0; n < 16; n++) {
        int col = n * 8 + t * 2;
        bool isA = col < 64;
        int c2 = isA ? col : col - 64;
        float* dst = isA ? g_hidA : g_hidB;
        const float* bp = isA ? biasA : biasB;
        float b0 = __ldg(bp + c2), b1 = __ldg(bp + c2 + 1);
        float o0 = fmaxf(acc[n][0] + b0, 0.f), o1 = fmaxf(acc[n][1] + b1, 0.f);
        float o2 = fmaxf(acc[n][2] + b0, 0.f), o3 = fmaxf(acc[n][3] + b1, 0.f);
        if (grow0 < nrows) *(float2*)(dst + grow0 * 64 + c2) = make_float2(o0, o1);
        if (grow1 < nrows) *(float2*)(dst + grow1 * 64 + c2) = make_float2(o2, o3);
    }
}

// ---------------- edge weights: one thread per edge, all 4 heads ----------------
__global__ void __launch_bounds__(256) wgt_k(const int* __restrict__ esmaxI) {
    int idx = blockIdx.x * blockDim.x + threadIdx.x;
    if (idx >= ET) return;
    int s = g_csrc[idx], d = g_cdst[idx];
    float4 esv = *(const float4*)(g_es + s * 4);
    float4 edv = *(const float4*)(g_ed + d * 4);
    float m0 = o2f(__ldg(esmaxI + 0)), m1 = o2f(__ldg(esmaxI + 1));
    float m2 = o2f(__ldg(esmaxI + 2)), m3 = o2f(__ldg(esmaxI + 3));
    float4 wv;
    {
        float e = esv.x + edv.x; e = (e > 0.f) ? e : 0.2f * e;
        float c = m0 + edv.x;    c = (c > 0.f) ? c : 0.2f * c;
        wv.x = __expf(e - c);
    }
    {
        float e = esv.y + edv.y; e = (e > 0.f) ? e : 0.2f * e;
        float c = m1 + edv.y;    c = (c > 0.f) ? c : 0.2f * c;
        wv.y = __expf(e - c);
    }
    {
        float e = esv.z + edv.z; e = (e > 0.f) ? e : 0.2f * e;
        float c = m2 + edv.z;    c = (c > 0.f) ? c : 0.2f * c;
        wv.z = __expf(e - c);
    }
    {
        float e = esv.w + edv.w; e = (e > 0.f) ? e : 0.2f * e;
        float c = m3 + edv.w;    c = (c > 0.f) ? c : 0.2f * c;
        wv.w = __expf(e - c);
    }
    *(float4*)(g_w + idx * 4) = wv;
}

// ---------------- gather: lean weighted aggregate + bias + residual + LN + relu ----------------
__global__ void __launch_bounds__(256) gather_k(float* __restrict__ h,
                                                const float* __restrict__ bc,
                                                const float* __restrict__ gam,
                                                const float* __restrict__ bet) {
    int d = (blockIdx.x * 256 + threadIdx.x) >> 5;
    if (d >= NN) return;
    int lane = threadIdx.x & 31;
    int hh = lane >> 3;
    int beg = g_rowstart[d], end = g_rowstart[d + 1];

    float ssum = 0.f;
    float4 acc = make_float4(0.f, 0.f, 0.f, 0.f);
    int i = beg;
    for (; i + 4 <= end; i += 4) {
        int s0 = __ldg(&g_csrc[i]);
        int s1 = __ldg(&g_csrc[i + 1]);
        int s2 = __ldg(&g_csrc[i + 2]);
        int s3 = __ldg(&g_csrc[i + 3]);
        float w0 = __ldg(&g_w[i * 4 + hh]);
        float w1 = __ldg(&g_w[(i + 1) * 4 + hh]);
        float w2 = __ldg(&g_w[(i + 2) * 4 + hh]);
        float w3 = __ldg(&g_w[(i + 3) * 4 + hh]);
        uint2 r0 = *(const uint2*)(g_xph + s0 * 128 + lane * 4);
        uint2 r1 = *(const uint2*)(g_xph + s1 * 128 + lane * 4);
        uint2 r2 = *(const uint2*)(g_xph + s2 * 128 + lane * 4);
        uint2 r3 = *(const uint2*)(g_xph + s3 * 128 + lane * 4);
        ssum += (w0 + w1) + (w2 + w3);
        float2 a0 = __half22float2(*(__half2*)&r0.x), b0 = __half22float2(*(__half2*)&r0.y);
        float2 a1 = __half22float2(*(__half2*)&r1.x), b1 = __half22float2(*(__half2*)&r1.y);
        float2 a2 = __half22float2(*(__half2*)&r2.x), b2 = __half22float2(*(__half2*)&r2.y);
        float2 a3 = __half22float2(*(__half2*)&r3.x), b3 = __half22float2(*(__half2*)&r3.y);
        acc.x = fmaf(w0, a0.x, fmaf(w1, a1.x, fmaf(w2, a2.x, fmaf(w3, a3.x, acc.x))));
        acc.y = fmaf(w0, a0.y, fmaf(w1, a1.y, fmaf(w2, a2.y, fmaf(w3, a3.y, acc.y))));
        acc.z = fmaf(w0, b0.x, fmaf(w1, b1.x, fmaf(w2, b2.x, fmaf(w3, b3.x, acc.z))));
        acc.w = fmaf(w0, b0.y, fmaf(w1, b1.y, fmaf(w2, b2.y, fmaf(w3, b3.y, acc.w))));
    }
    for (; i < end; i++) {
        int s0 = __ldg(&g_csrc[i]);
        float w0 = __ldg(&g_w[i * 4 + hh]);
        uint2 r0 = *(const uint2*)(g_xph + s0 * 128 + lane * 4);
        float2 a0 = __half22float2(*(__half2*)&r0.x), b0 = __half22float2(*(__half2*)&r0.y);
        ssum += w0;
        acc.x = fmaf(w0, a0.x, acc.x);
        acc.y = fmaf(w0, a0.y, acc.y);
        acc.z = fmaf(w0, b0.x, acc.z);
        acc.w = fmaf(w0, b0.y, acc.w);
    }
    float inv = 1.f / ssum;

    float4 hv = *(const float4*)(h + d * 128 + lane * 4);
    float4 bcv = *(const float4*)(bc + lane * 4);
    float4 y;
    y.x = acc.x * inv + bcv.x + hv.x;
    y.y = acc.y * inv + bcv.y + hv.y;
    y.z = acc.z * inv + bcv.z + hv.z;
    y.w = acc.w * inv + bcv.w + hv.w;

    float s1v = y.x + y.y + y.z + y.w;
#pragma unroll
    for (int off = 16; off >= 1; off >>= 1) s1v += __shfl_xor_sync(0xffffffffu, s1v, off);
    float mean = s1v * (1.f / 128.f);
    float dx = y.x - mean, dy = y.y - mean, dz = y.z - mean, dw = y.w - mean;
    float sq = dx * dx + dy * dy + dz * dz + dw * dw;
#pragma unroll
    for (int off = 16; off >= 1; off >>= 1) sq += __shfl_xor_sync(0xffffffffu, sq, off);
    float rstd = rsqrtf(sq * (1.f / 128.f) + 1e-5f);

    float4 g4 = *(const float4*)(gam + lane * 4);
    float4 b4 = *(const float4*)(bet + lane * 4);
    float4 o;
    o.x = fmaxf(dx * rstd * g4.x + b4.x, 0.f);
    o.y = fmaxf(dy * rstd * g4.y + b4.y, 0.f);
    o.z = fmaxf(dz * rstd * g4.z + b4.z, 0.f);
    o.w = fmaxf(dw * rstd * g4.w + b4.w, 0.f);
    *(float4*)(h + d * 128 + lane * 4) = o;
}

// ---------------- output heads ----------------
__device__ __forceinline__ float softplusf(float x) {
    if (x > 20.f) return x;
    return log1pf(__expf(x));
}

__global__ void __launch_bounds__(256) heads_k(const float* __restrict__ w2i,
                                               const float* __restrict__ b2i,
                                               const float* __restrict__ w2t,
                                               const float* __restrict__ b2t,
                                               float* __restrict__ out) {
    __shared__ float wi[64 * 3];
    __shared__ float wt[64 * 2];
    int t = threadIdx.x;
    if (t < 192) wi[t] = w2i[t];
    if (t < 128) wt[t] = w2t[t];
    __syncthreads();
    int n = blockIdx.x * 256 + t;
    if (n >= NN) return;
    float a0 = 0.f, a1 = 0.f, a2 = 0.f;
#pragma unroll 8
    for (int k = 0; k < 64; k++) {
        float v = g_hidA[n * 64 + k];
        a0 = fmaf(v, wi[k * 3 + 0], a0);
        a1 = fmaf(v, wi[k * 3 + 1], a1);
        a2 = fmaf(v, wi[k * 3 + 2], a2);
    }
    out[n * 3 + 0] = a0 + b2i[0];
    out[n * 3 + 1] = a1 + b2i[1];
    out[n * 3 + 2] = a2 + b2i[2];
    float t0 = 0.f, t1 = 0.f;
#pragma unroll 8
    for (int k = 0; k < 64; k++) {
        float v = g_hidB[n * 64 + k];
        t0 = fmaf(v, wt[k * 2 + 0], t0);
        t1 = fmaf(v, wt[k * 2 + 1], t1);
    }
    out[3 * NN + n * 2 + 0] = softplusf(t0 + b2t[0]);
    out[3 * NN + n * 2 + 1] = softplusf(t1 + b2t[1]);
}

// ---------------- launch ----------------
extern "C" void kernel_launch(void* const* d_in, const int* in_sizes, int n_in,
                              void* d_out, int out_size) {
    const float* x      = (const float*)d_in[0];
    const int*   ei     = (const int*)d_in[1];
    const float* enc_w1 = (const float*)d_in[2];
    const float* enc_b1 = (const float*)d_in[3];
    const float* enc_w2 = (const float*)d_in[4];
    const float* enc_b2 = (const float*)d_in[5];
    const float* W[3]  = {(const float*)d_in[6],  (const float*)d_in[12], (const float*)d_in[18]};
    const float* As[3] = {(const float*)d_in[7],  (const float*)d_in[13], (const float*)d_in[19]};
    const float* Ad[3] = {(const float*)d_in[8],  (const float*)d_in[14], (const float*)d_in[20]};
    const float* Bc[3] = {(const float*)d_in[9],  (const float*)d_in[15], (const float*)d_in[21]};
    const float* Gm[3] = {(const float*)d_in[10], (const float*)d_in[16], (const float*)d_in[22]};
    const float* Be[3] = {(const float*)d_in[11], (const float*)d_in[17], (const float*)d_in[23]};
    const float* imp_w1 = (const float*)d_in[24];
    const float* imp_b1 = (const float*)d_in[25];
    const float* imp_w2 = (const float*)d_in[26];
    const float* imp_b2 = (const float*)d_in[27];
    const float* tim_w1 = (const float*)d_in[28];
    const float* tim_b1 = (const float*)d_in[29];
    const float* tim_w2 = (const float*)d_in[30];
    const float* tim_b2 = (const float*)d_in[31];
    float* out = (float*)d_out;

    float *p_h, *p_tmp;
    cudaGetSymbolAddress((void**)&p_h, g_h);
    cudaGetSymbolAddress((void**)&p_tmp, g_tmp);
    int* p_esmax;
    cudaGetSymbolAddress((void**)&p_esmax, g_esmaxI);
    __nv_bfloat16 *p_wHi, *p_wLo;
    cudaGetSymbolAddress((void**)&p_wHi, g_wHi);
    cudaGetSymbolAddress((void**)&p_wLo, g_wLo);

    const int SMEM_128 = 69632 + 2 * 128 * LDB;  // 139264
    cudaFuncSetAttribute((const void*)mma_gemm_k<128, true, false, false>,
                         cudaFuncAttributeMaxDynamicSharedMemorySize, SMEM_128);
    cudaFuncSetAttribute((const void*)mma_gemm_k<128, false, false, true>,
                         cudaFuncAttributeMaxDynamicSharedMemorySize, SMEM_128);
    cudaFuncSetAttribute((const void*)mma_heads_k,
                         cudaFuncAttributeMaxDynamicSharedMemorySize, SMEM_128);

    const int NB = (NN + 127) / 128;  // 391

    // weight prep + CSR build (parallel scan)
    prep_w_k<<<6, 256>>>(enc_w2, W[0], W[1], W[2], imp_w1, tim_w1);
    init_deg_k<<<(NN + 255) / 256, 256>>>();
    count_k<<<(EE + 255) / 256, 256>>>(ei);
    partial_k<<<SCAN_B, 256>>>();
    scanb_k<<<1, SCAN_B>>>();
    fill_k<<<SCAN_B, 256>>>();
    scatter_k<<<(EE + 255) / 256, 256>>>(ei);

    // encoder
    enc1_k<<<2048, 128>>>(x, enc_w1, enc_b1, p_tmp);
    mma_gemm_k<128, true, false, false><<<NB, 256, SMEM_128>>>(
        p_tmp, p_wHi, p_wLo, enc_b2, nullptr, nullptr, nullptr, p_h, NN);

    // 3 GAT layers: GEMM(es/ed/esmax/fp16 xp) -> edge-parallel weights -> lean gather
    for (int l = 0; l < 3; l++) {
        mma_gemm_k<128, false, false, true><<<NB, 256, SMEM_128>>>(
            p_h, p_wHi + (1 + l) * 16384, p_wLo + (1 + l) * 16384, nullptr,
            As[l], Ad[l], p_esmax + l * 4, nullptr, NN);
        wgt_k<<<(ET + 255) / 256, 256>>>(p_esmax + l * 4);
        gather_k<<<(NN * 32 + 255) / 256, 256>>>(p_h, Bc[l], Gm[l], Be[l]);
    }

    // fused heads
    mma_heads_k<<<NB, 256, SMEM_128>>>(p_h, p_wHi + 4 * 16384, p_wLo + 4 * 16384,
                                       imp_b1, tim_b1, NN);
    heads_k<<<(NN + 255) / 256, 256>>>(imp_w2, imp_b2, tim_w2, tim_b2, out);
}

// round 10
// speedup vs baseline: 1.2576x; 1.2195x over previous
#include <cuda_runtime.h>
#include <cuda_fp16.h>
#include <math.h>
#include <stdint.h>

#define NN 50000
#define EE 1600000
#define ET (EE + NN)
#define HID 128
#define FIN 39

#define SCAN_B 64
#define SCAN_CH ((NN + SCAN_B - 1) / SCAN_B)  // 782 nodes per scan block

// ---------------- scratch (device globals; no allocation allowed) ----------------
__device__ float g_h[NN * HID];
__device__ float g_tmp[NN * HID];
__device__ __half g_xph[NN * HID];  // fp16 xp (gather is the only consumer)
__device__ float g_es[NN * 4];
__device__ float g_ed[NN * 4];
__device__ float g_w[ET * 4 + 32];  // per-edge per-head softmax numerators
__device__ float g_hidA[NN * 64];
__device__ float g_hidB[NN * 64];
__device__ int g_deg[NN];
__device__ int g_rowstart[NN + 1];
__device__ int g_cursor[NN];
__device__ int g_csrc[ET];
__device__ int g_cdst[ET];
__device__ int g_bsum[SCAN_B];
__device__ int g_bbase[SCAN_B];
__device__ int g_esmaxI[12];  // per-layer (3) x per-head (4) order-encoded float max
// pre-converted fp16 weight images, linear [N][K] (5 matrices + packed heads)
__device__ __half g_w16[6 * 128 * 128];

__device__ __forceinline__ int f2o(float f) {
    int i = __float_as_int(f);
    return i >= 0 ? i : (i ^ 0x7fffffff);
}
__device__ __forceinline__ float o2f(int i) {
    return __int_as_float(i >= 0 ? i : (i ^ 0x7fffffff));
}

// ---------------- CSR build ----------------
__global__ void init_deg_k() {
    int i = blockIdx.x * blockDim.x + threadIdx.x;
    if (i < NN) g_deg[i] = 1;  // self-loop pre-counted
    if (i < 12) g_esmaxI[i] = 0x80000000;  // order-encoded -inf
}

__global__ void count_k(const int* __restrict__ ei) {
    int idx = blockIdx.x * blockDim.x + threadIdx.x;
    if (idx >= EE) return;
    atomicAdd(&g_deg[ei[EE + idx]], 1);
}

// phase 1: per-block chunk sums of deg
__global__ void __launch_bounds__(256) partial_k() {
    __shared__ int ws[8];
    int b = blockIdx.x, t = threadIdx.x;
    int lo = b * SCAN_CH, hi = min(lo + SCAN_CH, NN);
    int s = 0;
    for (int i = lo + t; i < hi; i += 256) s += g_deg[i];
#pragma unroll
    for (int off = 16; off >= 1; off >>= 1) s += __shfl_xor_sync(0xffffffffu, s, off);
    if ((t & 31) == 0) ws[t >> 5] = s;
    __syncthreads();
    if (t < 8) {
        int v = ws[t];
#pragma unroll
        for (int off = 4; off >= 1; off >>= 1) v += __shfl_xor_sync(0xffu, v, off);
        if (t == 0) g_bsum[b] = v;
    }
}

// phase 2: exclusive scan of the 64 block sums
__global__ void __launch_bounds__(64) scanb_k() {
    __shared__ int sh[SCAN_B];
    int t = threadIdx.x;
    int v = g_bsum[t];
    sh[t] = v;
    __syncthreads();
    for (int off = 1; off < SCAN_B; off <<= 1) {
        int u = (t >= off) ? sh[t - off] : 0;
        __syncthreads();
        sh[t] += u;
        __syncthreads();
    }
    g_bbase[t] = (t == 0) ? 0 : sh[t - 1];
    if (t == 0) g_rowstart[NN] = ET;
}

// phase 3: local re-scan + write rowstart/cursor/self-loop csrc+cdst
__global__ void __launch_bounds__(256) fill_k() {
    __shared__ int sh[256];
    int b = blockIdx.x, t = threadIdx.x;
    int lo = b * SCAN_CH, hi = min(lo + SCAN_CH, NN);
    const int CH2 = (SCAN_CH + 255) / 256;  // 4
    int mylo = lo + t * CH2;
    int myhi = min(mylo + CH2, hi);
    int s = 0;
    for (int i = mylo; i < myhi; i++) s += g_deg[i];
    sh[t] = s;
    __syncthreads();
    for (int off = 1; off < 256; off <<= 1) {
        int u = (t >= off) ? sh[t - off] : 0;
        __syncthreads();
        sh[t] += u;
        __syncthreads();
    }
    int base = g_bbase[b] + ((t == 0) ? 0 : sh[t - 1]);
    for (int i = mylo; i < myhi; i++) {
        g_rowstart[i] = base;
        g_csrc[base] = i;  // self-loop
        g_cdst[base] = i;
        g_cursor[i] = base + 1;
        base += g_deg[i];
    }
}

__global__ void scatter_k(const int* __restrict__ ei) {
    int idx = blockIdx.x * blockDim.x + threadIdx.x;
    if (idx >= EE) return;
    int s = ei[idx], d = ei[EE + idx];
    int p = atomicAdd(&g_cursor[d], 1);
    g_csrc[p] = s;
    g_cdst[p] = d;
}

// ---------------- weight prep: transpose + fp16 convert, linear [N][K] ----------------
__global__ void __launch_bounds__(256) prep_w_k(const float* __restrict__ w0,
                                                const float* __restrict__ w1,
                                                const float* __restrict__ w2,
                                                const float* __restrict__ w3,
                                                const float* __restrict__ w4,
                                                const float* __restrict__ w5) {
    const float* Wm[6] = {w0, w1, w2, w3, w4, w5};
    const int ncs[6] = {128, 128, 128, 128, 64, 64};
    const int bases[6] = {0, 16384, 32768, 49152, 65536, 65536 + 8192};  // imp+tim packed
    int m = blockIdx.x;
    const float* B = Wm[m];
    int NC = ncs[m];
    __half* dst = g_w16 + bases[m];
    int total = NC * 128;
    for (int i = threadIdx.x; i < total; i += 256) {
        int n = i >> 7, k = i & 127;
        dst[i] = __float2half_rn(B[k * NC + n]);
    }
}

// ---------------- encoder layer 1 (K=39, FFMA) ----------------
__global__ void __launch_bounds__(128) enc1_k(const float* __restrict__ x,
                                              const float* __restrict__ W,
                                              const float* __restrict__ b,
                                              float* __restrict__ out) {
    __shared__ float Ws[FIN * 128];
    __shared__ float xs[4 * FIN];
    int t = threadIdx.x;
    for (int i = t; i < FIN * 128; i += 128) Ws[i] = W[i];
    float bb = b[t];
    for (int r0 = blockIdx.x * 4; r0 < NN; r0 += gridDim.x * 4) {
        __syncthreads();
        for (int i = t; i < 4 * FIN; i += 128) {
            int rr = i / FIN, k = i % FIN;
            int row = r0 + rr;
            xs[i] = (row < NN) ? x[row * FIN + k] : 0.f;
        }
        __syncthreads();
        float a0 = 0.f, a1 = 0.f, a2 = 0.f, a3 = 0.f;
#pragma unroll
        for (int k = 0; k < FIN; k++) {
            float w = Ws[k * 128 + t];
            a0 = fmaf(xs[k], w, a0);
            a1 = fmaf(xs[FIN + k], w, a1);
            a2 = fmaf(xs[2 * FIN + k], w, a2);
            a3 = fmaf(xs[3 * FIN + k], w, a3);
        }
        float acc[4] = {a0, a1, a2, a3};
#pragma unroll
        for (int rr = 0; rr < 4; rr++) {
            int row = r0 + rr;
            if (row < NN) out[row * 128 + t] = fmaxf(acc[rr] + bb, 0.f);
        }
    }
}

// ---------------- HMMA GEMM core pieces (single-pass fp16) ----------------
#define LDB 272  // padded smem row stride in bytes (136 fp16)

#define MMA16816(d, A0, A1, A2, A3, B0, B1)                                     \
    asm volatile(                                                               \
        "mma.sync.aligned.m16n8k16.row.col.f32.f16.f16.f32 "                    \
        "{%0,%1,%2,%3}, {%4,%5,%6,%7}, {%8,%9}, {%0,%1,%2,%3};"                 \
        : "+f"((d)[0]), "+f"((d)[1]), "+f"((d)[2]), "+f"((d)[3])                \
        : "r"(A0), "r"(A1), "r"(A2), "r"(A3), "r"(B0), "r"(B1))

// fill A (fp32 -> fp16) + B (pre-converted) into padded smem
template <int NC>
__device__ __forceinline__ void gemm_fill(const float* A, const __half* B16,
                                          char* sA, char* sB,
                                          int rb, int nrows, int tid) {
    for (int i = tid; i < 128 * 32; i += 256) {
        int r = i >> 5, c4 = (i & 31) * 4;
        float4 v = make_float4(0.f, 0.f, 0.f, 0.f);
        if (rb + r < nrows) v = *(const float4*)(A + (rb + r) * 128 + c4);
        __half2 p0 = __floats2half2_rn(v.x, v.y);
        __half2 p1 = __floats2half2_rn(v.z, v.w);
        *(uint2*)(sA + r * LDB + c4 * 2) = make_uint2(*(uint32_t*)&p0, *(uint32_t*)&p1);
    }
    for (int i = tid; i < NC * 16; i += 256) {
        int n = i >> 4, k8 = (i & 15) * 8;
        *(uint4*)(sB + n * LDB + k8 * 2) = ((const uint4*)B16)[i];
    }
}

template <int NCH>
__device__ __forceinline__ void gemm_main(const char* sA, const char* sB,
                                          int lrow0, int g, int t, float acc[][4]) {
#pragma unroll
    for (int n = 0; n < NCH; n++)
#pragma unroll
        for (int j = 0; j < 4; j++) acc[n][j] = 0.f;
#pragma unroll
    for (int ks = 0; ks < 8; ks++) {
        int kb = ks * 32 + t * 4;
        const char* pa = sA + lrow0 * LDB + kb;
        uint32_t a0 = *(const uint32_t*)(pa);
        uint32_t a1 = *(const uint32_t*)(pa + 8 * LDB);
        uint32_t a2 = *(const uint32_t*)(pa + 16);
        uint32_t a3 = *(const uint32_t*)(pa + 8 * LDB + 16);
#pragma unroll
        for (int n = 0; n < NCH; n++) {
            int col = n * 8 + g;
            const char* pb = sB + col * LDB + kb;
            uint32_t b0 = *(const uint32_t*)(pb);
            uint32_t b1 = *(const uint32_t*)(pb + 16);
            MMA16816(acc[n], a0, a1, a2, a3, b0, b1);
        }
    }
}

// main GEMM: ATTN -> write fp16 xp + es/ed + global es max (no fp32 C); else fp32 C (+bias)(+relu)
template <int NC, bool HAS_BIAS, bool RELU, bool ATTN>
__global__ void __launch_bounds__(256) mma_gemm_k(const float* __restrict__ A,
                                                  const __half* __restrict__ B16,
                                                  const float* __restrict__ bias,
                                                  const float* __restrict__ a_s,
                                                  const float* __restrict__ a_d,
                                                  int* __restrict__ esmaxI,
                                                  float* __restrict__ C, int nrows) {
    extern __shared__ char smem[];
    char* sA = smem;            // 128*272 = 34816
    char* sB = smem + 34816;    // NC*272
    __shared__ float s_max[8][4];

    int tid = threadIdx.x;
    int rb = blockIdx.x * 128;
    gemm_fill<NC>(A, B16, sA, sB, rb, nrows, tid);
    __syncthreads();

    int wid = tid >> 5, lane = tid & 31;
    int g = lane >> 2, t = lane & 3;
    int lrow0 = wid * 16 + g;
    constexpr int NCH = NC / 8;
    float acc[NCH][4];
    gemm_main<NCH>(sA, sB, lrow0, g, t, acc);

    int grow0 = rb + lrow0, grow1 = grow0 + 8;

    if (ATTN) {
        float es0[4], ed0[4], es1[4], ed1[4];
#pragma unroll
        for (int h = 0; h < 4; h++) { es0[h] = 0.f; ed0[h] = 0.f; es1[h] = 0.f; ed1[h] = 0.f; }
#pragma unroll
        for (int n = 0; n < NCH; n++) {
            int col = n * 8 + t * 2;
            int h = n >> 2;
            float as0 = __ldg(a_s + col), as1 = __ldg(a_s + col + 1);
            float ad0 = __ldg(a_d + col), ad1 = __ldg(a_d + col + 1);
            es0[h] += acc[n][0] * as0 + acc[n][1] * as1;
            ed0[h] += acc[n][0] * ad0 + acc[n][1] * ad1;
            es1[h] += acc[n][2] * as0 + acc[n][3] * as1;
            ed1[h] += acc[n][2] * ad0 + acc[n][3] * ad1;
        }
#pragma unroll
        for (int h = 0; h < 4; h++) {
            es0[h] += __shfl_xor_sync(0xffffffffu, es0[h], 1);
            es0[h] += __shfl_xor_sync(0xffffffffu, es0[h], 2);
            ed0[h] += __shfl_xor_sync(0xffffffffu, ed0[h], 1);
            ed0[h] += __shfl_xor_sync(0xffffffffu, ed0[h], 2);
            es1[h] += __shfl_xor_sync(0xffffffffu, es1[h], 1);
            es1[h] += __shfl_xor_sync(0xffffffffu, es1[h], 2);
            ed1[h] += __shfl_xor_sync(0xffffffffu, ed1[h], 1);
            ed1[h] += __shfl_xor_sync(0xffffffffu, ed1[h], 2);
        }
        if (t == 0) {
            if (grow0 < nrows) {
#pragma unroll
                for (int h = 0; h < 4; h++) {
                    g_es[grow0 * 4 + h] = es0[h];
                    g_ed[grow0 * 4 + h] = ed0[h];
                }
            }
            if (grow1 < nrows) {
#pragma unroll
                for (int h = 0; h < 4; h++) {
                    g_es[grow1 * 4 + h] = es1[h];
                    g_ed[grow1 * 4 + h] = ed1[h];
                }
            }
        }
        // block-level es max -> global atomicMax
        float wm[4];
#pragma unroll
        for (int h = 0; h < 4; h++) {
            wm[h] = fmaxf(es0[h], es1[h]);
#pragma unroll
            for (int off = 16; off >= 1; off >>= 1)
                wm[h] = fmaxf(wm[h], __shfl_xor_sync(0xffffffffu, wm[h], off));
        }
        if (lane == 0) {
#pragma unroll
            for (int h = 0; h < 4; h++) s_max[wid][h] = wm[h];
        }
        __syncthreads();
        if (wid == 0 && lane < 4) {
            float m = s_max[0][lane];
#pragma unroll
            for (int j = 1; j < 8; j++) m = fmaxf(m, s_max[j][lane]);
            atomicMax(&esmaxI[lane], f2o(m));
        }
        // store xp as fp16 only (gather is the sole consumer)
#pragma unroll
        for (int n = 0; n < NCH; n++) {
            int col = n * 8 + t * 2;
            __half2 p0 = __floats2half2_rn(acc[n][0], acc[n][1]);
            __half2 p1 = __floats2half2_rn(acc[n][2], acc[n][3]);
            if (grow0 < nrows) *(__half2*)(g_xph + grow0 * NC + col) = p0;
            if (grow1 < nrows) *(__half2*)(g_xph + grow1 * NC + col) = p1;
        }
        return;
    }

#pragma unroll
    for (int n = 0; n < NCH; n++) {
        int col = n * 8 + t * 2;
        float b0 = 0.f, b1 = 0.f;
        if (HAS_BIAS) { b0 = __ldg(bias + col); b1 = __ldg(bias + col + 1); }
        float o0 = acc[n][0] + b0, o1 = acc[n][1] + b1;
        float o2 = acc[n][2] + b0, o3 = acc[n][3] + b1;
        if (RELU) {
            o0 = fmaxf(o0, 0.f); o1 = fmaxf(o1, 0.f);
            o2 = fmaxf(o2, 0.f); o3 = fmaxf(o3, 0.f);
        }
        if (grow0 < nrows) *(float2*)(C + grow0 * NC + col) = make_float2(o0, o1);
        if (grow1 < nrows) *(float2*)(C + grow1 * NC + col) = make_float2(o2, o3);
    }
}

// fused heads GEMM: [imp_w1 | tim_w1] as one 128x128 B, split-store + relu
__global__ void __launch_bounds__(256) mma_heads_k(const float* __restrict__ A,
                                                   const __half* __restrict__ B16,
                                                   const float* __restrict__ biasA,
                                                   const float* __restrict__ biasB,
                                                   int nrows) {
    extern __shared__ char smem[];
    char* sA = smem;
    char* sB = smem + 34816;

    int tid = threadIdx.x;
    int rb = blockIdx.x * 128;
    gemm_fill<128>(A, B16, sA, sB, rb, nrows, tid);
    __syncthreads();

    int wid = tid >> 5, lane = tid & 31;
    int g = lane >> 2, t = lane & 3;
    int lrow0 = wid * 16 + g;
    float acc[16][4];
    gemm_main<16>(sA, sB, lrow0, g, t, acc);

    int grow0 = rb + lrow0, grow1 = grow0 + 8;
#pragma unroll
    for (int n = 0; n < 16; n++) {
        int col = n * 8 + t * 2;
        bool isA = col < 64;
        int c2 = isA ? col : col - 64;
        float* dst = isA ? g_hidA : g_hidB;
        const float* bp = isA ? biasA : biasB;
        float b0 = __ldg(bp + c2), b1 = __ldg(bp + c2 + 1);
        float o0 = fmaxf(acc[n][0] + b0, 0.f), o1 = fmaxf(acc[n][1] + b1, 0.f);
        float o2 = fmaxf(acc[n][2] + b0, 0.f), o3 = fmaxf(acc[n][3] + b1, 0.f);
        if (grow0 < nrows) *(float2*)(dst + grow0 * 64 + c2) = make_float2(o0, o1);
        if (grow1 < nrows) *(float2*)(dst + grow1 * 64 + c2) = make_float2(o2, o3);
    }
}

// ---------------- edge weights: one thread per edge, all 4 heads ----------------
__global__ void __launch_bounds__(256) wgt_k(const int* __restrict__ esmaxI) {
    int idx = blockIdx.x * blockDim.x + threadIdx.x;
    if (idx >= ET) return;
    int s = g_csrc[idx], d = g_cdst[idx];
    float4 esv = *(const float4*)(g_es + s * 4);
    float4 edv = *(const float4*)(g_ed + d * 4);
    float m0 = o2f(__ldg(esmaxI + 0)), m1 = o2f(__ldg(esmaxI + 1));
    float m2 = o2f(__ldg(esmaxI + 2)), m3 = o2f(__ldg(esmaxI + 3));
    float4 wv;
    {
        float e = esv.x + edv.x; e = (e > 0.f) ? e : 0.2f * e;
        float c = m0 + edv.x;    c = (c > 0.f) ? c : 0.2f * c;
        wv.x = __expf(e - c);
    }
    {
        float e = esv.y + edv.y; e = (e > 0.f) ? e : 0.2f * e;
        float c = m1 + edv.y;    c = (c > 0.f) ? c : 0.2f * c;
        wv.y = __expf(e - c);
    }
    {
        float e = esv.z + edv.z; e = (e > 0.f) ? e : 0.2f * e;
        float c = m2 + edv.z;    c = (c > 0.f) ? c : 0.2f * c;
        wv.z = __expf(e - c);
    }
    {
        float e = esv.w + edv.w; e = (e > 0.f) ? e : 0.2f * e;
        float c = m3 + edv.w;    c = (c > 0.f) ? c : 0.2f * c;
        wv.w = __expf(e - c);
    }
    *(float4*)(g_w + idx * 4) = wv;
}

// ---------------- gather: lean weighted aggregate + bias + residual + LN + relu ----------------
__global__ void __launch_bounds__(256) gather_k(float* __restrict__ h,
                                                const float* __restrict__ bc,
                                                const float* __restrict__ gam,
                                                const float* __restrict__ bet) {
    int d = (blockIdx.x * 256 + threadIdx.x) >> 5;
    if (d >= NN) return;
    int lane = threadIdx.x & 31;
    int hh = lane >> 3;
    int beg = g_rowstart[d], end = g_rowstart[d + 1];

    float ssum = 0.f;
    float4 acc = make_float4(0.f, 0.f, 0.f, 0.f);
    int i = beg;
    for (; i + 4 <= end; i += 4) {
        int s0 = __ldg(&g_csrc[i]);
        int s1 = __ldg(&g_csrc[i + 1]);
        int s2 = __ldg(&g_csrc[i + 2]);
        int s3 = __ldg(&g_csrc[i + 3]);
        float w0 = __ldg(&g_w[i * 4 + hh]);
        float w1 = __ldg(&g_w[(i + 1) * 4 + hh]);
        float w2 = __ldg(&g_w[(i + 2) * 4 + hh]);
        float w3 = __ldg(&g_w[(i + 3) * 4 + hh]);
        uint2 r0 = *(const uint2*)(g_xph + s0 * 128 + lane * 4);
        uint2 r1 = *(const uint2*)(g_xph + s1 * 128 + lane * 4);
        uint2 r2 = *(const uint2*)(g_xph + s2 * 128 + lane * 4);
        uint2 r3 = *(const uint2*)(g_xph + s3 * 128 + lane * 4);
        ssum += (w0 + w1) + (w2 + w3);
        float2 a0 = __half22float2(*(__half2*)&r0.x), b0 = __half22float2(*(__half2*)&r0.y);
        float2 a1 = __half22float2(*(__half2*)&r1.x), b1 = __half22float2(*(__half2*)&r1.y);
        float2 a2 = __half22float2(*(__half2*)&r2.x), b2 = __half22float2(*(__half2*)&r2.y);
        float2 a3 = __half22float2(*(__half2*)&r3.x), b3 = __half22float2(*(__half2*)&r3.y);
        acc.x = fmaf(w0, a0.x, fmaf(w1, a1.x, fmaf(w2, a2.x, fmaf(w3, a3.x, acc.x))));
        acc.y = fmaf(w0, a0.y, fmaf(w1, a1.y, fmaf(w2, a2.y, fmaf(w3, a3.y, acc.y))));
        acc.z = fmaf(w0, b0.x, fmaf(w1, b1.x, fmaf(w2, b2.x, fmaf(w3, b3.x, acc.z))));
        acc.w = fmaf(w0, b0.y, fmaf(w1, b1.y, fmaf(w2, b2.y, fmaf(w3, b3.y, acc.w))));
    }
    for (; i < end; i++) {
        int s0 = __ldg(&g_csrc[i]);
        float w0 = __ldg(&g_w[i * 4 + hh]);
        uint2 r0 = *(const uint2*)(g_xph + s0 * 128 + lane * 4);
        float2 a0 = __half22float2(*(__half2*)&r0.x), b0 = __half22float2(*(__half2*)&r0.y);
        ssum += w0;
        acc.x = fmaf(w0, a0.x, acc.x);
        acc.y = fmaf(w0, a0.y, acc.y);
        acc.z = fmaf(w0, b0.x, acc.z);
        acc.w = fmaf(w0, b0.y, acc.w);
    }
    float inv = 1.f / ssum;

    float4 hv = *(const float4*)(h + d * 128 + lane * 4);
    float4 bcv = *(const float4*)(bc + lane * 4);
    float4 y;
    y.x = acc.x * inv + bcv.x + hv.x;
    y.y = acc.y * inv + bcv.y + hv.y;
    y.z = acc.z * inv + bcv.z + hv.z;
    y.w = acc.w * inv + bcv.w + hv.w;

    float s1v = y.x + y.y + y.z + y.w;
#pragma unroll
    for (int off = 16; off >= 1; off >>= 1) s1v += __shfl_xor_sync(0xffffffffu, s1v, off);
    float mean = s1v * (1.f / 128.f);
    float dx = y.x - mean, dy = y.y - mean, dz = y.z - mean, dw = y.w - mean;
    float sq = dx * dx + dy * dy + dz * dz + dw * dw;
#pragma unroll
    for (int off = 16; off >= 1; off >>= 1) sq += __shfl_xor_sync(0xffffffffu, sq, off);
    float rstd = rsqrtf(sq * (1.f / 128.f) + 1e-5f);

    float4 g4 = *(const float4*)(gam + lane * 4);
    float4 b4 = *(const float4*)(bet + lane * 4);
    float4 o;
    o.x = fmaxf(dx * rstd * g4.x + b4.x, 0.f);
    o.y = fmaxf(dy * rstd * g4.y + b4.y, 0.f);
    o.z = fmaxf(dz * rstd * g4.z + b4.z, 0.f);
    o.w = fmaxf(dw * rstd * g4.w + b4.w, 0.f);
    *(float4*)(h + d * 128 + lane * 4) = o;
}

// ---------------- output heads ----------------
__device__ __forceinline__ float softplusf(float x) {
    if (x > 20.f) return x;
    return log1pf(__expf(x));
}

__global__ void __launch_bounds__(256) heads_k(const float* __restrict__ w2i,
                                               const float* __restrict__ b2i,
                                               const float* __restrict__ w2t,
                                               const float* __restrict__ b2t,
                                               float* __restrict__ out) {
    __shared__ float wi[64 * 3];
    __shared__ float wt[64 * 2];
    int t = threadIdx.x;
    if (t < 192) wi[t] = w2i[t];
    if (t < 128) wt[t] = w2t[t];
    __syncthreads();
    int n = blockIdx.x * 256 + t;
    if (n >= NN) return;
    float a0 = 0.f, a1 = 0.f, a2 = 0.f;
#pragma unroll 8
    for (int k = 0; k < 64; k++) {
        float v = g_hidA[n * 64 + k];
        a0 = fmaf(v, wi[k * 3 + 0], a0);
        a1 = fmaf(v, wi[k * 3 + 1], a1);
        a2 = fmaf(v, wi[k * 3 + 2], a2);
    }
    out[n * 3 + 0] = a0 + b2i[0];
    out[n * 3 + 1] = a1 + b2i[1];
    out[n * 3 + 2] = a2 + b2i[2];
    float t0 = 0.f, t1 = 0.f;
#pragma unroll 8
    for (int k = 0; k < 64; k++) {
        float v = g_hidB[n * 64 + k];
        t0 = fmaf(v, wt[k * 2 + 0], t0);
        t1 = fmaf(v, wt[k * 2 + 1], t1);
    }
    out[3 * NN + n * 2 + 0] = softplusf(t0 + b2t[0]);
    out[3 * NN + n * 2 + 1] = softplusf(t1 + b2t[1]);
}

// ---------------- launch ----------------
extern "C" void kernel_launch(void* const* d_in, const int* in_sizes, int n_in,
                              void* d_out, int out_size) {
    const float* x      = (const float*)d_in[0];
    const int*   ei     = (const int*)d_in[1];
    const float* enc_w1 = (const float*)d_in[2];
    const float* enc_b1 = (const float*)d_in[3];
    const float* enc_w2 = (const float*)d_in[4];
    const float* enc_b2 = (const float*)d_in[5];
    const float* W[3]  = {(const float*)d_in[6],  (const float*)d_in[12], (const float*)d_in[18]};
    const float* As[3] = {(const float*)d_in[7],  (const float*)d_in[13], (const float*)d_in[19]};
    const float* Ad[3] = {(const float*)d_in[8],  (const float*)d_in[14], (const float*)d_in[20]};
    const float* Bc[3] = {(const float*)d_in[9],  (const float*)d_in[15], (const float*)d_in[21]};
    const float* Gm[3] = {(const float*)d_in[10], (const float*)d_in[16], (const float*)d_in[22]};
    const float* Be[3] = {(const float*)d_in[11], (const float*)d_in[17], (const float*)d_in[23]};
    const float* imp_w1 = (const float*)d_in[24];
    const float* imp_b1 = (const float*)d_in[25];
    const float* imp_w2 = (const float*)d_in[26];
    const float* imp_b2 = (const float*)d_in[27];
    const float* tim_w1 = (const float*)d_in[28];
    const float* tim_b1 = (const float*)d_in[29];
    const float* tim_w2 = (const float*)d_in[30];
    const float* tim_b2 = (const float*)d_in[31];
    float* out = (float*)d_out;

    float *p_h, *p_tmp;
    cudaGetSymbolAddress((void**)&p_h, g_h);
    cudaGetSymbolAddress((void**)&p_tmp, g_tmp);
    int* p_esmax;
    cudaGetSymbolAddress((void**)&p_esmax, g_esmaxI);
    __half* p_w16;
    cudaGetSymbolAddress((void**)&p_w16, g_w16);

    const int SMEM_128 = 34816 + 128 * LDB;  // 69632
    cudaFuncSetAttribute((const void*)mma_gemm_k<128, true, false, false>,
                         cudaFuncAttributeMaxDynamicSharedMemorySize, SMEM_128);
    cudaFuncSetAttribute((const void*)mma_gemm_k<128, false, false, true>,
                         cudaFuncAttributeMaxDynamicSharedMemorySize, SMEM_128);
    cudaFuncSetAttribute((const void*)mma_heads_k,
                         cudaFuncAttributeMaxDynamicSharedMemorySize, SMEM_128);

    const int NB = (NN + 127) / 128;  // 391

    // weight prep + CSR build (parallel scan)
    prep_w_k<<<6, 256>>>(enc_w2, W[0], W[1], W[2], imp_w1, tim_w1);
    init_deg_k<<<(NN + 255) / 256, 256>>>();
    count_k<<<(EE + 255) / 256, 256>>>(ei);
    partial_k<<<SCAN_B, 256>>>();
    scanb_k<<<1, SCAN_B>>>();
    fill_k<<<SCAN_B, 256>>>();
    scatter_k<<<(EE + 255) / 256, 256>>>(ei);

    // encoder
    enc1_k<<<2048, 128>>>(x, enc_w1, enc_b1, p_tmp);
    mma_gemm_k<128, true, false, false><<<NB, 256, SMEM_128>>>(
        p_tmp, p_w16, enc_b2, nullptr, nullptr, nullptr, p_h, NN);

    // 3 GAT layers: GEMM(es/ed/esmax/fp16 xp) -> edge-parallel weights -> lean gather
    for (int l = 0; l < 3; l++) {
        mma_gemm_k<128, false, false, true><<<NB, 256, SMEM_128>>>(
            p_h, p_w16 + (1 + l) * 16384, nullptr,
            As[l], Ad[l], p_esmax + l * 4, nullptr, NN);
        wgt_k<<<(ET + 255) / 256, 256>>>(p_esmax + l * 4);
        gather_k<<<(NN * 32 + 255) / 256, 256>>>(p_h, Bc[l], Gm[l], Be[l]);
    }

    // fused heads
    mma_heads_k<<<NB, 256, SMEM_128>>>(p_h, p_w16 + 4 * 16384, imp_b1, tim_b1, NN);
    heads_k<<<(NN + 255) / 256, 256>>>(imp_w2, imp_b2, tim_w2, tim_b2, out);
}